// round 2
// baseline (speedup 1.0000x reference)
#include <cuda_runtime.h>
#include <math_constants.h>

// Problem constants
#define BB 8
#define C1 128
#define C2 256
#define NN 1024
#define HEADS 8
#define DD 32
#define KC 3
#define SCALE 0.17677669529663687f  // 32^-0.5

// Scratch (device globals; no allocation allowed)
__device__ float g_xf[BB * C2 * NN];        // proj_in output = identity, [b][c][n]
__device__ float g_prob[BB * KC * NN];      // cluster probs   [b][k][n]
__device__ float g_qkv[BB * 3 * C2 * NN];   // qkv             [b][o][n], o = part*256 + h*32 + d
__device__ float g_att[BB * C2 * NN];       // attention out   [b][c][n], c = h*32 + d

// ---------------------------------------------------------------------------
// Tiled fp32 GEMM: C[bz] = A(MxK) @ B[bz](KxN)  (+ Res[bz] optionally)
// A shared across batch, row-major. 128x128 tile, BK=8, 256 threads, 8x8 micro.
// Requires M%128==0, N%128==0, K%8==0 (true for all three uses).
// ---------------------------------------------------------------------------
template <bool ADD_RES>
__global__ __launch_bounds__(256) void gemm128(
    const float* __restrict__ A, const float* __restrict__ Bmat,
    float* __restrict__ C, const float* __restrict__ Res,
    int M, int N, int K)
{
    const int n0 = blockIdx.x * 128;
    const int m0 = blockIdx.y * 128;
    const int bz = blockIdx.z;
    Bmat += (size_t)bz * K * N;
    C    += (size_t)bz * M * N;
    const float* R = ADD_RES ? (Res + (size_t)bz * M * N) : nullptr;

    __shared__ float As[8][132];
    __shared__ float Bs[8][128];

    const int t  = threadIdx.x;
    const int tx = t & 15;
    const int ty = t >> 4;

    const int am = t >> 1;        // 0..127 (A row within tile)
    const int ak = (t & 1) * 4;   // 0 or 4
    const int bk = t >> 5;        // 0..7
    const int bn = (t & 31) * 4;  // 0..124

    float acc[8][8];
#pragma unroll
    for (int i = 0; i < 8; i++)
#pragma unroll
        for (int j = 0; j < 8; j++) acc[i][j] = 0.f;

    for (int kt = 0; kt < K; kt += 8) {
        float4 av = *(const float4*)&A[(size_t)(m0 + am) * K + kt + ak];
        float4 bv = *(const float4*)&Bmat[(size_t)(kt + bk) * N + n0 + bn];
        __syncthreads();
        As[ak + 0][am] = av.x;
        As[ak + 1][am] = av.y;
        As[ak + 2][am] = av.z;
        As[ak + 3][am] = av.w;
        *(float4*)&Bs[bk][bn] = bv;
        __syncthreads();
#pragma unroll
        for (int kk = 0; kk < 8; kk++) {
            float a[8], b[8];
#pragma unroll
            for (int i = 0; i < 8; i++) a[i] = As[kk][ty + 16 * i];
#pragma unroll
            for (int j = 0; j < 8; j++) b[j] = Bs[kk][tx + 16 * j];
#pragma unroll
            for (int i = 0; i < 8; i++)
#pragma unroll
                for (int j = 0; j < 8; j++) acc[i][j] += a[i] * b[j];
        }
    }

#pragma unroll
    for (int i = 0; i < 8; i++) {
        const int m = m0 + ty + 16 * i;
#pragma unroll
        for (int j = 0; j < 8; j++) {
            const int n = n0 + tx + 16 * j;
            const size_t idx = (size_t)m * N + n;
            float v = acc[i][j];
            if (ADD_RES) v += R[idx];
            C[idx] = v;
        }
    }
}

// ---------------------------------------------------------------------------
// Cluster logits + softmax over KC=3.  grid (4 chunks, 8 batches), 256 threads.
// ---------------------------------------------------------------------------
__global__ __launch_bounds__(256) void cluster_kernel(
    const float* __restrict__ Wc, const float* __restrict__ bc)
{
    const int b = blockIdx.y;
    const int n = blockIdx.x * 256 + threadIdx.x;

    __shared__ float Wcs[KC][C2];
    __shared__ float bcs[KC];
    for (int i = threadIdx.x; i < KC * C2; i += 256) Wcs[i / C2][i % C2] = Wc[i];
    if (threadIdx.x < KC) bcs[threadIdx.x] = bc[threadIdx.x];
    __syncthreads();

    const float* xb = g_xf + (size_t)b * C2 * NN;
    float a0 = bcs[0], a1 = bcs[1], a2 = bcs[2];
#pragma unroll 4
    for (int c = 0; c < C2; c++) {
        float xv = xb[(size_t)c * NN + n];
        a0 += Wcs[0][c] * xv;
        a1 += Wcs[1][c] * xv;
        a2 += Wcs[2][c] * xv;
    }
    float mm = fmaxf(a0, fmaxf(a1, a2));
    float e0 = __expf(a0 - mm), e1 = __expf(a1 - mm), e2 = __expf(a2 - mm);
    float inv = 1.f / (e0 + e1 + e2);
    g_prob[(size_t)(b * KC + 0) * NN + n] = e0 * inv;
    g_prob[(size_t)(b * KC + 1) * NN + n] = e1 * inv;
    g_prob[(size_t)(b * KC + 2) * NN + n] = e2 * inv;
}

// ---------------------------------------------------------------------------
// Clustered attention.  S_i[n,m] = pq_i[n]*pk_i[m]*(SCALE*q.k) — raw q.k
// computed ONCE per tile, 3 online softmaxes reuse it.
// grid (32 q-tiles, 8 heads, 8 batches), 256 threads.
// Per block: TQ=32 queries, loop over 16 key tiles of TK=64.
// Warp w owns q rows 4w..4w+3; lane = output dim d (0..31).
// ---------------------------------------------------------------------------
__global__ __launch_bounds__(256) void attn_kernel()
{
    const int q0 = blockIdx.x * 32;
    const int h  = blockIdx.y;
    const int b  = blockIdx.z;

    __shared__ float Qs[32][33];      // [d][q]
    __shared__ float Ks[32][65];      // [d][k]
    __shared__ float Vs[32][65];      // [d][k]
    __shared__ float Ss[32][65];      // [q][k]  raw scaled q.k
    __shared__ float Pbuf[8][4][64];  // per-warp P tile
    __shared__ float probQs[KC][32];
    __shared__ float probKs[KC][64];

    const int t    = threadIdx.x;
    const int lane = t & 31;
    const int w    = t >> 5;
    const int tx   = t & 15;
    const int ty   = t >> 4;

    const float* qbase = g_qkv + (size_t)(b * 768 + 0   + h * DD) * NN;
    const float* kbase = g_qkv + (size_t)(b * 768 + 256 + h * DD) * NN;
    const float* vbase = g_qkv + (size_t)(b * 768 + 512 + h * DD) * NN;
    const float* pbase = g_prob + (size_t)b * KC * NN;

    // Load Q tile [32d x 32q] and probQ
#pragma unroll
    for (int j = 0; j < 4; j++) {
        int i = t + 256 * j;
        int d = i >> 5, qq = i & 31;
        Qs[d][qq] = qbase[(size_t)d * NN + q0 + qq];
    }
    if (t < KC * 32) {
        int ci = t >> 5, qq = t & 31;
        probQs[ci][qq] = pbase[(size_t)ci * NN + q0 + qq];
    }

    float m_[KC][4], l_[KC][4], acc_[KC][4];
#pragma unroll
    for (int i = 0; i < KC; i++)
#pragma unroll
        for (int r = 0; r < 4; r++) { m_[i][r] = -1e30f; l_[i][r] = 0.f; acc_[i][r] = 0.f; }

    for (int k0 = 0; k0 < NN; k0 += 64) {
        __syncthreads();
        // Load K, V tiles [32d x 64k] + probK
#pragma unroll
        for (int j = 0; j < 8; j++) {
            int i = t + 256 * j;
            int d = i >> 6, kk = i & 63;
            Ks[d][kk] = kbase[(size_t)d * NN + k0 + kk];
            Vs[d][kk] = vbase[(size_t)d * NN + k0 + kk];
        }
        if (t < KC * 64) {
            int ci = t / 64, kk = t & 63;
            probKs[ci][kk] = pbase[(size_t)ci * NN + k0 + kk];
        }
        __syncthreads();

        // S tile: rows {ty, ty+16}, cols {tx + 16j}
        float sa[2][4];
#pragma unroll
        for (int ii = 0; ii < 2; ii++)
#pragma unroll
            for (int jj = 0; jj < 4; jj++) sa[ii][jj] = 0.f;
#pragma unroll
        for (int d = 0; d < 32; d++) {
            float a0 = Qs[d][ty], a1 = Qs[d][ty + 16];
            float b0 = Ks[d][tx], b1 = Ks[d][tx + 16], b2 = Ks[d][tx + 32], b3 = Ks[d][tx + 48];
            sa[0][0] += a0 * b0; sa[0][1] += a0 * b1; sa[0][2] += a0 * b2; sa[0][3] += a0 * b3;
            sa[1][0] += a1 * b0; sa[1][1] += a1 * b1; sa[1][2] += a1 * b2; sa[1][3] += a1 * b3;
        }
#pragma unroll
        for (int ii = 0; ii < 2; ii++)
#pragma unroll
            for (int jj = 0; jj < 4; jj++)
                Ss[ty + 16 * ii][tx + 16 * jj] = sa[ii][jj] * SCALE;
        __syncthreads();

        // 3 online softmaxes + PV, reusing the raw S tile
#pragma unroll
        for (int i = 0; i < KC; i++) {
            const float pk1 = probKs[i][lane];
            const float pk2 = probKs[i][lane + 32];
#pragma unroll
            for (int r = 0; r < 4; r++) {
                const int qr = w * 4 + r;
                const float pq = probQs[i][qr];
                float t1 = pq * pk1 * Ss[qr][lane];
                float t2 = pq * pk2 * Ss[qr][lane + 32];
                float tm = fmaxf(t1, t2);
#pragma unroll
                for (int off = 16; off; off >>= 1)
                    tm = fmaxf(tm, __shfl_xor_sync(0xffffffffu, tm, off));
                float mnew  = fmaxf(m_[i][r], tm);
                float alpha = __expf(m_[i][r] - mnew);
                float p1 = __expf(t1 - mnew), p2 = __expf(t2 - mnew);
                float ls = p1 + p2;
#pragma unroll
                for (int off = 16; off; off >>= 1)
                    ls += __shfl_xor_sync(0xffffffffu, ls, off);
                m_[i][r] = mnew;
                l_[i][r] = l_[i][r] * alpha + ls;
                acc_[i][r] *= alpha;
                Pbuf[w][r][lane]      = p1;
                Pbuf[w][r][lane + 32] = p2;
            }
            __syncwarp();
            // acc[r][d=lane] += sum_k P[r][k] * pk_i[k] * V[k][lane]
#pragma unroll 4
            for (int k = 0; k < 64; k++) {
                float wv = probKs[i][k] * Vs[lane][k];
                acc_[i][0] += Pbuf[w][0][k] * wv;
                acc_[i][1] += Pbuf[w][1][k] * wv;
                acc_[i][2] += Pbuf[w][2][k] * wv;
                acc_[i][3] += Pbuf[w][3][k] * wv;
            }
            __syncwarp();
        }
    }

    __syncthreads();
    // Stage output in smem (reuse Ss as [d][q]) then write coalesced
#pragma unroll
    for (int r = 0; r < 4; r++) {
        float o = (acc_[0][r] / l_[0][r] + acc_[1][r] / l_[1][r] + acc_[2][r] / l_[2][r]) * (1.f / KC);
        Ss[lane][w * 4 + r] = o;
    }
    __syncthreads();
    float* obase = g_att + (size_t)(b * C2 + h * DD) * NN;
#pragma unroll
    for (int j = 0; j < 4; j++) {
        int i = t + 256 * j;
        int d = i >> 5, qq = i & 31;
        obase[(size_t)d * NN + q0 + qq] = Ss[d][qq];
    }
}

// ---------------------------------------------------------------------------
extern "C" void kernel_launch(void* const* d_in, const int* in_sizes, int n_in,
                              void* d_out, int out_size)
{
    const float* x         = (const float*)d_in[0];
    const float* W_in      = (const float*)d_in[1];
    const float* W_cluster = (const float*)d_in[2];
    const float* b_cluster = (const float*)d_in[3];
    const float* W_qkv     = (const float*)d_in[4];
    const float* W_proj    = (const float*)d_in[5];
    float* out = (float*)d_out;

    float *xf, *qkv, *att;
    cudaGetSymbolAddress((void**)&xf,  g_xf);
    cudaGetSymbolAddress((void**)&qkv, g_qkv);
    cudaGetSymbolAddress((void**)&att, g_att);

    // proj_in: xf[b] (256x1024) = W_in (256x128) @ x[b] (128x1024)
    gemm128<false><<<dim3(NN / 128, C2 / 128, BB), 256>>>(W_in, x, xf, nullptr, C2, NN, C1);
    // cluster probs
    cluster_kernel<<<dim3(4, BB), 256>>>(W_cluster, b_cluster);
    // qkv: (768x1024) = W_qkv (768x256) @ xf
    gemm128<false><<<dim3(NN / 128, 768 / 128, BB), 256>>>(W_qkv, xf, qkv, nullptr, 3 * C2, NN, C2);
    // clustered attention
    attn_kernel<<<dim3(NN / 32, HEADS, BB), 256>>>();
    // proj_out + residual: out = W_proj @ att + xf
    gemm128<true><<<dim3(NN / 128, C2 / 128, BB), 256>>>(W_proj, att, out, xf, C2, NN, C2);
}

// round 3
// speedup vs baseline: 2.7858x; 2.7858x over previous
#include <cuda_runtime.h>

// Problem constants
#define BB 8
#define C1 128
#define C2 256
#define NN 1024
#define HEADS 8
#define DD 32
#define KC 3
#define SCALE 0.17677669529663687f  // 32^-0.5
#define LOG2E 1.4426950408889634f

// Scratch (device globals; no allocation allowed)
__device__ float g_xf[BB * C2 * NN];        // proj_in output = identity, [b][c][n]
__device__ float g_prob[BB * KC * NN];      // cluster probs   [b][k][n]
__device__ float g_qkv[BB * 3 * C2 * NN];   // qkv             [b][o][n]
__device__ float g_att[BB * C2 * NN];       // attention out   [b][c][n]

// ---------------------------------------------------------------------------
__device__ __forceinline__ unsigned f2tf(float x) {
    unsigned r; asm("cvt.rna.tf32.f32 %0, %1;" : "=r"(r) : "f"(x)); return r;
}
__device__ __forceinline__ float ex2(float x) {
    float r; asm("ex2.approx.f32 %0, %1;" : "=f"(r) : "f"(x)); return r;
}
__device__ __forceinline__ void mma8(
    float& c0, float& c1, float& c2, float& c3,
    unsigned a0, unsigned a1, unsigned a2, unsigned a3,
    unsigned b0, unsigned b1)
{
    asm volatile(
        "mma.sync.aligned.m16n8k8.row.col.f32.tf32.tf32.f32 "
        "{%0,%1,%2,%3}, {%4,%5,%6,%7}, {%8,%9}, {%0,%1,%2,%3};"
        : "+f"(c0), "+f"(c1), "+f"(c2), "+f"(c3)
        : "r"(a0), "r"(a1), "r"(a2), "r"(a3), "r"(b0), "r"(b1));
}

// ---------------------------------------------------------------------------
// Tiled fp32 GEMM: C[bz] = A(MxK) @ B[bz](KxN)  (+ Res[bz] optionally)
// ---------------------------------------------------------------------------
template <bool ADD_RES>
__global__ __launch_bounds__(256) void gemm128(
    const float* __restrict__ A, const float* __restrict__ Bmat,
    float* __restrict__ C, const float* __restrict__ Res,
    int M, int N, int K)
{
    const int n0 = blockIdx.x * 128;
    const int m0 = blockIdx.y * 128;
    const int bz = blockIdx.z;
    Bmat += (size_t)bz * K * N;
    C    += (size_t)bz * M * N;
    const float* R = ADD_RES ? (Res + (size_t)bz * M * N) : nullptr;

    __shared__ float As[8][132];
    __shared__ float Bs[8][128];

    const int t  = threadIdx.x;
    const int tx = t & 15;
    const int ty = t >> 4;

    const int am = t >> 1;
    const int ak = (t & 1) * 4;
    const int bk = t >> 5;
    const int bn = (t & 31) * 4;

    float acc[8][8];
#pragma unroll
    for (int i = 0; i < 8; i++)
#pragma unroll
        for (int j = 0; j < 8; j++) acc[i][j] = 0.f;

    for (int kt = 0; kt < K; kt += 8) {
        float4 av = *(const float4*)&A[(size_t)(m0 + am) * K + kt + ak];
        float4 bv = *(const float4*)&Bmat[(size_t)(kt + bk) * N + n0 + bn];
        __syncthreads();
        As[ak + 0][am] = av.x;
        As[ak + 1][am] = av.y;
        As[ak + 2][am] = av.z;
        As[ak + 3][am] = av.w;
        *(float4*)&Bs[bk][bn] = bv;
        __syncthreads();
#pragma unroll
        for (int kk = 0; kk < 8; kk++) {
            float a[8], b[8];
#pragma unroll
            for (int i = 0; i < 8; i++) a[i] = As[kk][ty + 16 * i];
#pragma unroll
            for (int j = 0; j < 8; j++) b[j] = Bs[kk][tx + 16 * j];
#pragma unroll
            for (int i = 0; i < 8; i++)
#pragma unroll
                for (int j = 0; j < 8; j++) acc[i][j] += a[i] * b[j];
        }
    }

#pragma unroll
    for (int i = 0; i < 8; i++) {
        const int m = m0 + ty + 16 * i;
#pragma unroll
        for (int j = 0; j < 8; j++) {
            const int n = n0 + tx + 16 * j;
            const size_t idx = (size_t)m * N + n;
            float v = acc[i][j];
            if (ADD_RES) v += R[idx];
            C[idx] = v;
        }
    }
}

// ---------------------------------------------------------------------------
// Cluster logits + softmax over KC=3
// ---------------------------------------------------------------------------
__global__ __launch_bounds__(256) void cluster_kernel(
    const float* __restrict__ Wc, const float* __restrict__ bc)
{
    const int b = blockIdx.y;
    const int n = blockIdx.x * 256 + threadIdx.x;

    __shared__ float Wcs[KC][C2];
    __shared__ float bcs[KC];
    for (int i = threadIdx.x; i < KC * C2; i += 256) Wcs[i / C2][i % C2] = Wc[i];
    if (threadIdx.x < KC) bcs[threadIdx.x] = bc[threadIdx.x];
    __syncthreads();

    const float* xb = g_xf + (size_t)b * C2 * NN;
    float a0 = bcs[0], a1 = bcs[1], a2 = bcs[2];
#pragma unroll 4
    for (int c = 0; c < C2; c++) {
        float xv = xb[(size_t)c * NN + n];
        a0 += Wcs[0][c] * xv;
        a1 += Wcs[1][c] * xv;
        a2 += Wcs[2][c] * xv;
    }
    float mm = fmaxf(a0, fmaxf(a1, a2));
    float e0 = __expf(a0 - mm), e1 = __expf(a1 - mm), e2 = __expf(a2 - mm);
    float inv = 1.f / (e0 + e1 + e2);
    g_prob[(size_t)(b * KC + 0) * NN + n] = e0 * inv;
    g_prob[(size_t)(b * KC + 1) * NN + n] = e1 * inv;
    g_prob[(size_t)(b * KC + 2) * NN + n] = e2 * inv;
}

// ---------------------------------------------------------------------------
// Clustered attention via tf32 mma.sync.
// Block: 128 threads (4 warps), q-tile 64 (warp w owns 16 rows), k-tile 64.
// S raw = Q@K^T computed ONCE per tile (tensor pipe); 3 online softmaxes in
// exp2 domain reuse it; P'(=P*pk) staged per-warp in smem; PV via mma.
// grid (16 q-tiles, 8 heads, 8 batches).
// ---------------------------------------------------------------------------
__global__ __launch_bounds__(128) void attn_kernel()
{
    const int q0 = blockIdx.x * 64;
    const int h  = blockIdx.y;
    const int b  = blockIdx.z;
    const int t    = threadIdx.x;
    const int lane = t & 31;
    const int w    = t >> 5;
    const int g    = lane >> 2;   // group id (0..7)
    const int tg   = lane & 3;    // thread-in-group (0..3)

    __shared__ __align__(16) unsigned Qs[64][37];   // [q][d]  tf32, transposed load
    __shared__ __align__(16) unsigned Ks[64][37];   // [key][d] tf32
    __shared__ __align__(16) unsigned Vs[32][68];   // [d][key] tf32
    __shared__ __align__(16) unsigned Ps[4][16][68];// per-warp P' tf32
    __shared__ float probQs[KC][64];
    __shared__ float probKs[KC][64];

    const float* qb = g_qkv + (size_t)(b * 768 + 0   + h * DD) * NN;
    const float* kb = g_qkv + (size_t)(b * 768 + 256 + h * DD) * NN;
    const float* vb = g_qkv + (size_t)(b * 768 + 512 + h * DD) * NN;
    const float* pb = g_prob + (size_t)b * KC * NN;

    // Q tile: gmem [d][tok] -> smem [tok][d] (tf32)
#pragma unroll
    for (int j = 0; j < 16; j++) {
        int i = t + 128 * j, d = i >> 6, tok = i & 63;
        Qs[tok][d] = f2tf(qb[(size_t)d * NN + q0 + tok]);
    }
    for (int i = t; i < KC * 64; i += 128)
        probQs[i >> 6][i & 63] = pb[(size_t)(i >> 6) * NN + q0 + (i & 63)];

    const int rq0 = 16 * w + g;
    const int rq1 = rq0 + 8;

    float m_[KC][2], l_[KC][2], acc[KC][4][4];
#pragma unroll
    for (int i = 0; i < KC; i++) {
        m_[i][0] = -1e30f; m_[i][1] = -1e30f;
        l_[i][0] = 0.f;    l_[i][1] = 0.f;
#pragma unroll
        for (int jn = 0; jn < 4; jn++)
#pragma unroll
            for (int e = 0; e < 4; e++) acc[i][jn][e] = 0.f;
    }

    for (int k0 = 0; k0 < NN; k0 += 64) {
        __syncthreads();
        // K tile: [d][tok] -> [tok][d]; V tile: [d][tok] direct
#pragma unroll
        for (int j = 0; j < 16; j++) {
            int i = t + 128 * j, d = i >> 6, tok = i & 63;
            Ks[tok][d] = f2tf(kb[(size_t)d * NN + k0 + tok]);
        }
#pragma unroll
        for (int j = 0; j < 16; j++) {
            int i = t + 128 * j, d = i >> 6, tok = i & 63;
            Vs[d][tok] = f2tf(vb[(size_t)d * NN + k0 + tok]);
        }
        for (int i = t; i < KC * 64; i += 128)
            probKs[i >> 6][i & 63] = pb[(size_t)(i >> 6) * NN + k0 + (i & 63)];
        __syncthreads();

        // S[16x64] per warp = Q @ K^T   (raw, unscaled)
        float S[8][4];
#pragma unroll
        for (int j = 0; j < 8; j++)
#pragma unroll
            for (int e = 0; e < 4; e++) S[j][e] = 0.f;
#pragma unroll
        for (int kk = 0; kk < 32; kk += 8) {
            unsigned a0 = Qs[rq0][kk + tg],     a1 = Qs[rq1][kk + tg];
            unsigned a2 = Qs[rq0][kk + tg + 4], a3 = Qs[rq1][kk + tg + 4];
#pragma unroll
            for (int j = 0; j < 8; j++) {
                unsigned b0 = Ks[j * 8 + g][kk + tg];
                unsigned b1 = Ks[j * 8 + g][kk + tg + 4];
                mma8(S[j][0], S[j][1], S[j][2], S[j][3], a0, a1, a2, a3, b0, b1);
            }
        }

        // 3 online softmaxes (exp2 domain) + PV, reusing raw S
#pragma unroll
        for (int i = 0; i < KC; i++) {
            const float qc0 = probQs[i][rq0] * (SCALE * LOG2E);
            const float qc1 = probQs[i][rq1] * (SCALE * LOG2E);

            float mx0 = -1e30f, mx1 = -1e30f;
#pragma unroll
            for (int j = 0; j < 8; j++) {
                float pk0 = probKs[i][j * 8 + 2 * tg];
                float pk1 = probKs[i][j * 8 + 2 * tg + 1];
                mx0 = fmaxf(mx0, fmaxf(qc0 * (pk0 * S[j][0]), qc0 * (pk1 * S[j][1])));
                mx1 = fmaxf(mx1, fmaxf(qc1 * (pk0 * S[j][2]), qc1 * (pk1 * S[j][3])));
            }
            mx0 = fmaxf(mx0, __shfl_xor_sync(0xffffffffu, mx0, 1));
            mx0 = fmaxf(mx0, __shfl_xor_sync(0xffffffffu, mx0, 2));
            mx1 = fmaxf(mx1, __shfl_xor_sync(0xffffffffu, mx1, 1));
            mx1 = fmaxf(mx1, __shfl_xor_sync(0xffffffffu, mx1, 2));

            float mn0 = fmaxf(m_[i][0], mx0), mn1 = fmaxf(m_[i][1], mx1);
            float al0 = ex2(m_[i][0] - mn0),  al1 = ex2(m_[i][1] - mn1);
            m_[i][0] = mn0; m_[i][1] = mn1;

            float ls0 = 0.f, ls1 = 0.f;
#pragma unroll
            for (int j = 0; j < 8; j++) {
                float pk0 = probKs[i][j * 8 + 2 * tg];
                float pk1 = probKs[i][j * 8 + 2 * tg + 1];
                float p00 = ex2(qc0 * (pk0 * S[j][0]) - mn0);
                float p01 = ex2(qc0 * (pk1 * S[j][1]) - mn0);
                float p10 = ex2(qc1 * (pk0 * S[j][2]) - mn1);
                float p11 = ex2(qc1 * (pk1 * S[j][3]) - mn1);
                ls0 += p00 + p01;
                ls1 += p10 + p11;
                uint2 v0 = make_uint2(f2tf(p00 * pk0), f2tf(p01 * pk1));
                uint2 v1 = make_uint2(f2tf(p10 * pk0), f2tf(p11 * pk1));
                *(uint2*)&Ps[w][g][j * 8 + 2 * tg]     = v0;
                *(uint2*)&Ps[w][g + 8][j * 8 + 2 * tg] = v1;
            }
            ls0 += __shfl_xor_sync(0xffffffffu, ls0, 1);
            ls0 += __shfl_xor_sync(0xffffffffu, ls0, 2);
            ls1 += __shfl_xor_sync(0xffffffffu, ls1, 1);
            ls1 += __shfl_xor_sync(0xffffffffu, ls1, 2);
            l_[i][0] = l_[i][0] * al0 + ls0;
            l_[i][1] = l_[i][1] * al1 + ls1;
#pragma unroll
            for (int jn = 0; jn < 4; jn++) {
                acc[i][jn][0] *= al0; acc[i][jn][1] *= al0;
                acc[i][jn][2] *= al1; acc[i][jn][3] *= al1;
            }
            __syncwarp();
            // acc += P' @ V    (A = Ps[16x64], B = Vs as [n=d][k=key])
#pragma unroll
            for (int kk = 0; kk < 8; kk++) {
                unsigned a0 = Ps[w][g][kk * 8 + tg];
                unsigned a1 = Ps[w][g + 8][kk * 8 + tg];
                unsigned a2 = Ps[w][g][kk * 8 + tg + 4];
                unsigned a3 = Ps[w][g + 8][kk * 8 + tg + 4];
#pragma unroll
                for (int jn = 0; jn < 4; jn++) {
                    unsigned b0 = Vs[jn * 8 + g][kk * 8 + tg];
                    unsigned b1 = Vs[jn * 8 + g][kk * 8 + tg + 4];
                    mma8(acc[i][jn][0], acc[i][jn][1], acc[i][jn][2], acc[i][jn][3],
                         a0, a1, a2, a3, b0, b1);
                }
            }
            __syncwarp();
        }
    }

    // Epilogue: combine clusters, stage [d][q] in smem (reuse Qs), write out
    __syncthreads();
    float* Os = (float*)&Qs[0][0];  // [32][65]
    float r0[KC], r1[KC];
#pragma unroll
    for (int i = 0; i < KC; i++) {
        r0[i] = 1.f / (3.f * l_[i][0]);
        r1[i] = 1.f / (3.f * l_[i][1]);
    }
#pragma unroll
    for (int jn = 0; jn < 4; jn++) {
        int d0 = jn * 8 + 2 * tg;
        float o0 = acc[0][jn][0] * r0[0] + acc[1][jn][0] * r0[1] + acc[2][jn][0] * r0[2];
        float o1 = acc[0][jn][1] * r0[0] + acc[1][jn][1] * r0[1] + acc[2][jn][1] * r0[2];
        float o2 = acc[0][jn][2] * r1[0] + acc[1][jn][2] * r1[1] + acc[2][jn][2] * r1[2];
        float o3 = acc[0][jn][3] * r1[0] + acc[1][jn][3] * r1[1] + acc[2][jn][3] * r1[2];
        Os[d0 * 65 + rq0]       = o0;
        Os[(d0 + 1) * 65 + rq0] = o1;
        Os[d0 * 65 + rq1]       = o2;
        Os[(d0 + 1) * 65 + rq1] = o3;
    }
    __syncthreads();
    float* ob = g_att + (size_t)(b * C2 + h * DD) * NN;
#pragma unroll
    for (int j = 0; j < 16; j++) {
        int i = t + 128 * j, d = i >> 6, q = i & 63;
        ob[(size_t)d * NN + q0 + q] = Os[d * 65 + q];
    }
}

// ---------------------------------------------------------------------------
extern "C" void kernel_launch(void* const* d_in, const int* in_sizes, int n_in,
                              void* d_out, int out_size)
{
    const float* x         = (const float*)d_in[0];
    const float* W_in      = (const float*)d_in[1];
    const float* W_cluster = (const float*)d_in[2];
    const float* b_cluster = (const float*)d_in[3];
    const float* W_qkv     = (const float*)d_in[4];
    const float* W_proj    = (const float*)d_in[5];
    float* out = (float*)d_out;

    float *xf, *qkv, *att;
    cudaGetSymbolAddress((void**)&xf,  g_xf);
    cudaGetSymbolAddress((void**)&qkv, g_qkv);
    cudaGetSymbolAddress((void**)&att, g_att);

    gemm128<false><<<dim3(NN / 128, C2 / 128, BB), 256>>>(W_in, x, xf, nullptr, C2, NN, C1);
    cluster_kernel<<<dim3(4, BB), 256>>>(W_cluster, b_cluster);
    gemm128<false><<<dim3(NN / 128, 768 / 128, BB), 256>>>(W_qkv, xf, qkv, nullptr, 3 * C2, NN, C2);
    attn_kernel<<<dim3(NN / 64, HEADS, BB), 256 >> 1>>>();
    gemm128<true><<<dim3(NN / 128, C2 / 128, BB), 256>>>(W_proj, att, out, xf, C2, NN, C2);
}

// round 5
// speedup vs baseline: 6.9626x; 2.4994x over previous
#include <cuda_runtime.h>
#include <cuda_bf16.h>

// Problem constants
#define BB 8
#define C1 128
#define C2 256
#define NN 1024
#define HEADS 8
#define DD 32
#define KC 3
#define SCALE 0.17677669529663687f  // 32^-0.5
#define LOG2E 1.4426950408889634f

// Scratch (device globals; no allocation allowed)
__device__ float g_xf[BB * C2 * NN];        // proj_in output = identity, [b][c][n]
__device__ float g_prob[BB * KC * NN];      // cluster probs   [b][k][n]
__device__ float g_qkv[BB * 3 * C2 * NN];   // qkv             [b][o][n]
__device__ float g_att[BB * C2 * NN];       // attention out   [b][c][n]

// ---------------------------------------------------------------------------
__device__ __forceinline__ float ex2(float x) {
    float r; asm("ex2.approx.f32 %0, %1;" : "=f"(r) : "f"(x)); return r;
}
// pack two f32 -> bf16x2, lo in bits[0:16)
__device__ __forceinline__ unsigned pack_bf2(float lo, float hi) {
    unsigned r;
    asm("cvt.rn.bf16x2.f32 %0, %1, %2;" : "=r"(r) : "f"(hi), "f"(lo));
    return r;
}
__device__ __forceinline__ unsigned saddr(const void* p) {
    return (unsigned)__cvta_generic_to_shared(p);
}
__device__ __forceinline__ void ldsm4(unsigned& r0, unsigned& r1, unsigned& r2, unsigned& r3, unsigned a) {
    asm volatile("ldmatrix.sync.aligned.m8n8.x4.shared.b16 {%0,%1,%2,%3}, [%4];"
                 : "=r"(r0), "=r"(r1), "=r"(r2), "=r"(r3) : "r"(a));
}
__device__ __forceinline__ void ldsm4t(unsigned& r0, unsigned& r1, unsigned& r2, unsigned& r3, unsigned a) {
    asm volatile("ldmatrix.sync.aligned.m8n8.x4.trans.shared.b16 {%0,%1,%2,%3}, [%4];"
                 : "=r"(r0), "=r"(r1), "=r"(r2), "=r"(r3) : "r"(a));
}
__device__ __forceinline__ void mma16(float* c, const unsigned* a, unsigned b0, unsigned b1) {
    asm volatile(
        "mma.sync.aligned.m16n8k16.row.col.f32.bf16.bf16.f32 "
        "{%0,%1,%2,%3}, {%4,%5,%6,%7}, {%8,%9}, {%0,%1,%2,%3};"
        : "+f"(c[0]), "+f"(c[1]), "+f"(c[2]), "+f"(c[3])
        : "r"(a[0]), "r"(a[1]), "r"(a[2]), "r"(a[3]), "r"(b0), "r"(b1));
}

// ---------------------------------------------------------------------------
// fp32 SIMT GEMM (kept for proj_in: feeds the residual identity path)
// ---------------------------------------------------------------------------
__global__ __launch_bounds__(256) void gemm128(
    const float* __restrict__ A, const float* __restrict__ Bmat,
    float* __restrict__ C, int M, int N, int K)
{
    const int n0 = blockIdx.x * 128;
    const int m0 = blockIdx.y * 128;
    const int bz = blockIdx.z;
    Bmat += (size_t)bz * K * N;
    C    += (size_t)bz * M * N;

    __shared__ float As[8][132];
    __shared__ float Bs[8][128];

    const int t  = threadIdx.x;
    const int tx = t & 15;
    const int ty = t >> 4;
    const int am = t >> 1;
    const int ak = (t & 1) * 4;
    const int bk = t >> 5;
    const int bn = (t & 31) * 4;

    float acc[8][8];
#pragma unroll
    for (int i = 0; i < 8; i++)
#pragma unroll
        for (int j = 0; j < 8; j++) acc[i][j] = 0.f;

    for (int kt = 0; kt < K; kt += 8) {
        float4 av = *(const float4*)&A[(size_t)(m0 + am) * K + kt + ak];
        float4 bv = *(const float4*)&Bmat[(size_t)(kt + bk) * N + n0 + bn];
        __syncthreads();
        As[ak + 0][am] = av.x;
        As[ak + 1][am] = av.y;
        As[ak + 2][am] = av.z;
        As[ak + 3][am] = av.w;
        *(float4*)&Bs[bk][bn] = bv;
        __syncthreads();
#pragma unroll
        for (int kk = 0; kk < 8; kk++) {
            float a[8], b[8];
#pragma unroll
            for (int i = 0; i < 8; i++) a[i] = As[kk][ty + 16 * i];
#pragma unroll
            for (int j = 0; j < 8; j++) b[j] = Bs[kk][tx + 16 * j];
#pragma unroll
            for (int i = 0; i < 8; i++)
#pragma unroll
                for (int j = 0; j < 8; j++) acc[i][j] += a[i] * b[j];
        }
    }
#pragma unroll
    for (int i = 0; i < 8; i++)
#pragma unroll
        for (int j = 0; j < 8; j++)
            C[(size_t)(m0 + ty + 16 * i) * N + n0 + tx + 16 * j] = acc[i][j];
}

// ---------------------------------------------------------------------------
// bf16 tensor-core GEMM: C[bz] = A(MxK)@B[bz](KxN) (+Res[bz])
// 128x128 tile, kstep 32, 8 warps (2x4), each warp 64x32 via m16n8k16.
// ---------------------------------------------------------------------------
template <bool ADD_RES>
__global__ __launch_bounds__(256, 2) void gemm_bf16(
    const float* __restrict__ A, const float* __restrict__ Bmat,
    float* __restrict__ C, const float* __restrict__ Res,
    int M, int N, int K)
{
    const int n0 = blockIdx.x * 128;
    const int m0 = blockIdx.y * 128;
    const int bz = blockIdx.z;
    Bmat += (size_t)bz * K * N;
    C    += (size_t)bz * M * N;
    const float* R = ADD_RES ? (Res + (size_t)bz * M * N) : nullptr;

    __shared__ __align__(16) __nv_bfloat16 As[128][40];
    __shared__ __align__(16) __nv_bfloat16 Bs[32][136];

    const int t    = threadIdx.x;
    const int lane = t & 31;
    const int w    = t >> 5;
    const int g    = lane >> 2;
    const int tg   = lane & 3;
    const int wm   = (w >> 2) * 64;
    const int wn   = (w & 3) * 32;

    float acc[4][4][4];
#pragma unroll
    for (int mb = 0; mb < 4; mb++)
#pragma unroll
        for (int nb = 0; nb < 4; nb++)
#pragma unroll
            for (int e = 0; e < 4; e++) acc[mb][nb][e] = 0.f;

    const int lam = t >> 3, lak = (t & 7) * 4;
    const int lbk = t >> 5, lbn = (t & 31) * 4;

    for (int kt = 0; kt < K; kt += 32) {
        __syncthreads();
#pragma unroll
        for (int p = 0; p < 4; p++) {
            float4 v = *(const float4*)&A[(size_t)(m0 + lam + 32 * p) * K + kt + lak];
            *(unsigned*)&As[lam + 32 * p][lak]     = pack_bf2(v.x, v.y);
            *(unsigned*)&As[lam + 32 * p][lak + 2] = pack_bf2(v.z, v.w);
        }
#pragma unroll
        for (int p = 0; p < 4; p++) {
            float4 v = *(const float4*)&Bmat[(size_t)(kt + lbk + 8 * p) * N + n0 + lbn];
            *(unsigned*)&Bs[lbk + 8 * p][lbn]     = pack_bf2(v.x, v.y);
            *(unsigned*)&Bs[lbk + 8 * p][lbn + 2] = pack_bf2(v.z, v.w);
        }
        __syncthreads();
#pragma unroll
        for (int ks = 0; ks < 2; ks++) {
            unsigned a[4][4], bb[2][4];
#pragma unroll
            for (int mb = 0; mb < 4; mb++) {
                int row = wm + 16 * mb + (lane & 7) + ((lane & 8) ? 8 : 0);
                int col = 16 * ks + ((lane >= 16) ? 8 : 0);
                ldsm4(a[mb][0], a[mb][1], a[mb][2], a[mb][3], saddr(&As[row][col]));
            }
#pragma unroll
            for (int np = 0; np < 2; np++) {
                int row = 16 * ks + (lane & 7) + ((lane & 8) ? 8 : 0);
                int col = wn + 16 * np + ((lane >= 16) ? 8 : 0);
                ldsm4t(bb[np][0], bb[np][1], bb[np][2], bb[np][3], saddr(&Bs[row][col]));
            }
#pragma unroll
            for (int mb = 0; mb < 4; mb++)
#pragma unroll
                for (int nb = 0; nb < 4; nb++)
                    mma16(acc[mb][nb], a[mb], bb[nb >> 1][(nb & 1) * 2], bb[nb >> 1][(nb & 1) * 2 + 1]);
        }
    }

#pragma unroll
    for (int mb = 0; mb < 4; mb++) {
        const int mr = m0 + wm + 16 * mb;
#pragma unroll
        for (int nb = 0; nb < 4; nb++) {
            const int nc = n0 + wn + 8 * nb + 2 * tg;
            const size_t i0 = (size_t)(mr + g) * N + nc;
            const size_t i1 = (size_t)(mr + g + 8) * N + nc;
            float2 v0 = make_float2(acc[mb][nb][0], acc[mb][nb][1]);
            float2 v1 = make_float2(acc[mb][nb][2], acc[mb][nb][3]);
            if (ADD_RES) {
                float2 r0 = *(const float2*)&R[i0];
                float2 r1 = *(const float2*)&R[i1];
                v0.x += r0.x; v0.y += r0.y; v1.x += r1.x; v1.y += r1.y;
            }
            *(float2*)&C[i0] = v0;
            *(float2*)&C[i1] = v1;
        }
    }
}

// ---------------------------------------------------------------------------
// Cluster logits + softmax over KC=3
// ---------------------------------------------------------------------------
__global__ __launch_bounds__(256) void cluster_kernel(
    const float* __restrict__ Wc, const float* __restrict__ bc)
{
    const int b = blockIdx.y;
    const int n = blockIdx.x * 256 + threadIdx.x;

    __shared__ float Wcs[KC][C2];
    __shared__ float bcs[KC];
    for (int i = threadIdx.x; i < KC * C2; i += 256) Wcs[i / C2][i % C2] = Wc[i];
    if (threadIdx.x < KC) bcs[threadIdx.x] = bc[threadIdx.x];
    __syncthreads();

    const float* xb = g_xf + (size_t)b * C2 * NN;
    float a0 = bcs[0], a1 = bcs[1], a2 = bcs[2];
#pragma unroll 4
    for (int c = 0; c < C2; c++) {
        float xv = xb[(size_t)c * NN + n];
        a0 += Wcs[0][c] * xv;
        a1 += Wcs[1][c] * xv;
        a2 += Wcs[2][c] * xv;
    }
    float mm = fmaxf(a0, fmaxf(a1, a2));
    float e0 = __expf(a0 - mm), e1 = __expf(a1 - mm), e2 = __expf(a2 - mm);
    float inv = 1.f / (e0 + e1 + e2);
    g_prob[(size_t)(b * KC + 0) * NN + n] = e0 * inv;
    g_prob[(size_t)(b * KC + 1) * NN + n] = e1 * inv;
    g_prob[(size_t)(b * KC + 2) * NN + n] = e2 * inv;
}

// ---------------------------------------------------------------------------
// Clustered attention, bf16 mma + register-resident P.
// 128 threads (4 warps), q-tile 64 (warp w: rows 16w..16w+15), k-tile 64.
// Raw S = Q@K^T once per tile; 3 no-max exp2 softmaxes reuse it; P packed
// directly into mma A-fragments (no smem); PV via mma with ldmatrix V frags.
// ---------------------------------------------------------------------------
#define QP 72  // bf16 pitch for Qds/Kds/Vds
__global__ __launch_bounds__(128, 3) void attn_kernel()
{
    const int q0 = blockIdx.x * 64;
    const int h  = blockIdx.y;
    const int b  = blockIdx.z;
    const int t    = threadIdx.x;
    const int lane = t & 31;
    const int w    = t >> 5;
    const int g    = lane >> 2;
    const int tg   = lane & 3;

    __shared__ __align__(16) char sm[15360];
    __nv_bfloat16* Qds = (__nv_bfloat16*)(sm);          // [32][72]
    __nv_bfloat16* Kds = (__nv_bfloat16*)(sm + 4608);   // [32][72]
    __nv_bfloat16* Vds = (__nv_bfloat16*)(sm + 9216);   // [32][72]
    float* probQs = (float*)(sm + 13824);               // [3][64]
    float* probKs = (float*)(sm + 14592);               // [3][64]
    float* Os = (float*)sm;                             // [32][65] (epilogue, overlays Qds+Kds)

    const float* qb = g_qkv + (size_t)(b * 768 + h * DD) * NN;
    const float* kb = qb + (size_t)256 * NN;
    const float* vb = qb + (size_t)512 * NN;
    const float* pb = g_prob + (size_t)b * KC * NN;

    // Q tile: gmem [d][tok] fp32 -> smem bf16 [d][tok]
    const int ld  = t >> 4;
    const int lt4 = (t & 15) * 4;
#pragma unroll
    for (int p = 0; p < 4; p++) {
        float4 v = *(const float4*)&qb[(size_t)(ld + 8 * p) * NN + q0 + lt4];
        *(unsigned*)&Qds[(ld + 8 * p) * QP + lt4]     = pack_bf2(v.x, v.y);
        *(unsigned*)&Qds[(ld + 8 * p) * QP + lt4 + 2] = pack_bf2(v.z, v.w);
    }
    if (t < KC * 64) probQs[t] = pb[(size_t)(t >> 6) * NN + q0 + (t & 63)];
    __syncthreads();

    // Q fragments (loop invariant): A of m16n8k16, rows q, k = d
    unsigned aQ[2][4];
#pragma unroll
    for (int ds = 0; ds < 2; ds++) {
        int row = 16 * ds + (lane & 7) + ((lane >= 16) ? 8 : 0);
        int col = 16 * w + ((lane & 8) ? 8 : 0);
        ldsm4t(aQ[ds][0], aQ[ds][1], aQ[ds][2], aQ[ds][3], saddr(&Qds[row * QP + col]));
    }
    float qc[KC][2];
#pragma unroll
    for (int i = 0; i < KC; i++) {
        qc[i][0] = probQs[i * 64 + 16 * w + g]     * (SCALE * LOG2E);
        qc[i][1] = probQs[i * 64 + 16 * w + g + 8] * (SCALE * LOG2E);
    }

    float acc[KC][4][4];
    float lacc[KC][2];
#pragma unroll
    for (int i = 0; i < KC; i++) {
        lacc[i][0] = 0.f; lacc[i][1] = 0.f;
#pragma unroll
        for (int jn = 0; jn < 4; jn++)
#pragma unroll
            for (int e = 0; e < 4; e++) acc[i][jn][e] = 0.f;
    }

    for (int k0 = 0; k0 < NN; k0 += 64) {
        __syncthreads();
#pragma unroll
        for (int p = 0; p < 4; p++) {
            float4 kv = *(const float4*)&kb[(size_t)(ld + 8 * p) * NN + k0 + lt4];
            float4 vv = *(const float4*)&vb[(size_t)(ld + 8 * p) * NN + k0 + lt4];
            *(unsigned*)&Kds[(ld + 8 * p) * QP + lt4]     = pack_bf2(kv.x, kv.y);
            *(unsigned*)&Kds[(ld + 8 * p) * QP + lt4 + 2] = pack_bf2(kv.z, kv.w);
            *(unsigned*)&Vds[(ld + 8 * p) * QP + lt4]     = pack_bf2(vv.x, vv.y);
            *(unsigned*)&Vds[(ld + 8 * p) * QP + lt4 + 2] = pack_bf2(vv.z, vv.w);
        }
        if (t < KC * 64) probKs[t] = pb[(size_t)(t >> 6) * NN + k0 + (t & 63)];
        __syncthreads();

        // S[16 x 64] per warp = Q @ K^T (raw)
        float S[8][4];
#pragma unroll
        for (int j = 0; j < 8; j++)
#pragma unroll
            for (int e = 0; e < 4; e++) S[j][e] = 0.f;
#pragma unroll
        for (int ds = 0; ds < 2; ds++) {
#pragma unroll
            for (int jp = 0; jp < 4; jp++) {
                unsigned b0a, b1a, b0b, b1b;
                int row = 16 * ds + (lane & 7) + ((lane & 8) ? 8 : 0);
                int col = 16 * jp + ((lane >= 16) ? 8 : 0);
                ldsm4t(b0a, b1a, b0b, b1b, saddr(&Kds[row * QP + col]));
                mma16(S[2 * jp],     aQ[ds], b0a, b1a);
                mma16(S[2 * jp + 1], aQ[ds], b0b, b1b);
            }
        }

        // 3 softmaxes (no-max, exp2 domain) + PV; P stays in registers
#pragma unroll
        for (int i = 0; i < KC; i++) {
            const float q0c = qc[i][0], q1c = qc[i][1];
            unsigned aP[4][4];
#pragma unroll
            for (int j = 0; j < 8; j++) {
                float pk0 = probKs[i * 64 + 8 * j + 2 * tg];
                float pk1 = probKs[i * 64 + 8 * j + 2 * tg + 1];
                float p00 = ex2(q0c * pk0 * S[j][0]);
                float p01 = ex2(q0c * pk1 * S[j][1]);
                float p10 = ex2(q1c * pk0 * S[j][2]);
                float p11 = ex2(q1c * pk1 * S[j][3]);
                lacc[i][0] += p00 + p01;
                lacc[i][1] += p10 + p11;
                aP[j >> 1][(j & 1) * 2]     = pack_bf2(p00 * pk0, p01 * pk1);
                aP[j >> 1][(j & 1) * 2 + 1] = pack_bf2(p10 * pk0, p11 * pk1);
            }
#pragma unroll
            for (int kk = 0; kk < 4; kk++) {
#pragma unroll
                for (int jp = 0; jp < 2; jp++) {
                    unsigned v0, v1, v2, v3;
                    int row = 8 * (2 * jp + ((lane >= 16) ? 1 : 0)) + (lane & 7);
                    int col = 16 * kk + ((lane & 8) ? 8 : 0);
                    ldsm4(v0, v1, v2, v3, saddr(&Vds[row * QP + col]));
                    mma16(acc[i][2 * jp],     aP[kk], v0, v1);
                    mma16(acc[i][2 * jp + 1], aP[kk], v2, v3);
                }
            }
        }
    }

    // Epilogue: reduce l over quad, combine clusters, stage [d][q], write out
    __syncthreads();
    float r0[KC], r1[KC];
#pragma unroll
    for (int i = 0; i < KC; i++) {
        float l0 = lacc[i][0];
        l0 += __shfl_xor_sync(0xffffffffu, l0, 1);
        l0 += __shfl_xor_sync(0xffffffffu, l0, 2);
        float l1 = lacc[i][1];
        l1 += __shfl_xor_sync(0xffffffffu, l1, 1);
        l1 += __shfl_xor_sync(0xffffffffu, l1, 2);
        r0[i] = 1.f / (3.f * l0);
        r1[i] = 1.f / (3.f * l1);
    }
    const int qg  = 16 * w + g;
#pragma unroll
    for (int jn = 0; jn < 4; jn++) {
        int d0 = 8 * jn + 2 * tg;
        float o00 = acc[0][jn][0] * r0[0] + acc[1][jn][0] * r0[1] + acc[2][jn][0] * r0[2];
        float o01 = acc[0][jn][1] * r0[0] + acc[1][jn][1] * r0[1] + acc[2][jn][1] * r0[2];
        float o10 = acc[0][jn][2] * r1[0] + acc[1][jn][2] * r1[1] + acc[2][jn][2] * r1[2];
        float o11 = acc[0][jn][3] * r1[0] + acc[1][jn][3] * r1[1] + acc[2][jn][3] * r1[2];
        Os[d0 * 65 + qg]           = o00;
        Os[(d0 + 1) * 65 + qg]     = o01;
        Os[d0 * 65 + qg + 8]       = o10;
        Os[(d0 + 1) * 65 + qg + 8] = o11;
    }
    __syncthreads();
    float* ob = g_att + (size_t)(b * C2 + h * DD) * NN;
#pragma unroll
    for (int j = 0; j < 16; j++) {
        int i = t + 128 * j, d = i >> 6, q = i & 63;
        ob[(size_t)d * NN + q0 + q] = Os[d * 65 + q];
    }
}

// ---------------------------------------------------------------------------
extern "C" void kernel_launch(void* const* d_in, const int* in_sizes, int n_in,
                              void* d_out, int out_size)
{
    const float* x         = (const float*)d_in[0];
    const float* W_in      = (const float*)d_in[1];
    const float* W_cluster = (const float*)d_in[2];
    const float* b_cluster = (const float*)d_in[3];
    const float* W_qkv     = (const float*)d_in[4];
    const float* W_proj    = (const float*)d_in[5];
    float* out = (float*)d_out;

    float *xf, *qkv, *att;
    cudaGetSymbolAddress((void**)&xf,  g_xf);
    cudaGetSymbolAddress((void**)&qkv, g_qkv);
    cudaGetSymbolAddress((void**)&att, g_att);

    // proj_in (fp32 — residual identity path)
    gemm128<<<dim3(NN / 128, C2 / 128, BB), 256>>>(W_in, x, xf, C2, NN, C1);
    // cluster probs
    cluster_kernel<<<dim3(4, BB), 256>>>(W_cluster, b_cluster);
    // qkv (bf16 tensor)
    gemm_bf16<false><<<dim3(NN / 128, 768 / 128, BB), 256>>>(W_qkv, xf, qkv, nullptr, 3 * C2, NN, C2);
    // clustered attention (bf16 tensor)
    attn_kernel<<<dim3(NN / 64, HEADS, BB), 128>>>();
    // proj_out + residual (bf16 tensor, fp32 residual add)
    gemm_bf16<true><<<dim3(NN / 128, C2 / 128, BB), 256>>>(W_proj, att, out, xf, C2, NN, C2);
}